// round 7
// baseline (speedup 1.0000x reference)
#include <cuda_runtime.h>
#include <cmath>

#define B_TOTAL 1024
#define H 256
#define HP 128

// Scratch (allocation-free): intermediate activations
__device__ float g_x3[B_TOTAL * HP];   // 512 KB
__device__ float g_g1[B_TOTAL * H];    // 1 MB

// ---------------------------------------------------------------------------
// Kernel 1: h = cc*h0 + (1-cc)*ht ; x3 = tanh(fc3 @ tanh(fc2 @ tanh(fc1 @ h)))
// 128 CTAs x 256 threads, 8 batches per CTA.
// ---------------------------------------------------------------------------
__global__ __launch_bounds__(256) void mlp_head_kernel(
    const float* __restrict__ h0, const float* __restrict__ ht,
    const float* __restrict__ cin,
    const float* __restrict__ w1,   // [HP, H]
    const float* __restrict__ w2,   // [HP, HP]
    const float* __restrict__ w3)   // [HP, HP]
{
    __shared__ float hs[8][H];
    __shared__ float xa[8][HP];
    __shared__ float xb[8][HP];

    const int b0   = blockIdx.x * 8;
    const int tid  = threadIdx.x;
    const int warp = tid >> 5;
    const int lane = tid & 31;

    const float cc = fminf(fmaxf(cin[0], 0.0f), 1.0f);

    // blend h into shared
    for (int i = tid; i < 8 * H; i += 256) {
        const int bb = i >> 8;
        const int hh = i & (H - 1);
        const int g  = (b0 + bb) * H + hh;
        hs[bb][hh] = cc * h0[g] + (1.0f - cc) * ht[g];
    }
    __syncthreads();

    // stage 1: [HP] = tanh(w1 [HP,H] @ h [H])
    for (int p = warp; p < HP; p += 8) {
        float wr[8];
#pragma unroll
        for (int j = 0; j < 8; j++) wr[j] = w1[p * H + lane + 32 * j];
#pragma unroll
        for (int bb = 0; bb < 8; bb++) {
            float acc = 0.0f;
#pragma unroll
            for (int j = 0; j < 8; j++) acc = fmaf(wr[j], hs[bb][lane + 32 * j], acc);
#pragma unroll
            for (int off = 16; off > 0; off >>= 1)
                acc += __shfl_xor_sync(0xffffffffu, acc, off);
            if (lane == 0) xa[bb][p] = tanhf(acc);
        }
    }
    __syncthreads();

    // stage 2: [HP] = tanh(w2 [HP,HP] @ x1)
    for (int p = warp; p < HP; p += 8) {
        float wr[4];
#pragma unroll
        for (int j = 0; j < 4; j++) wr[j] = w2[p * HP + lane + 32 * j];
#pragma unroll
        for (int bb = 0; bb < 8; bb++) {
            float acc = 0.0f;
#pragma unroll
            for (int j = 0; j < 4; j++) acc = fmaf(wr[j], xa[bb][lane + 32 * j], acc);
#pragma unroll
            for (int off = 16; off > 0; off >>= 1)
                acc += __shfl_xor_sync(0xffffffffu, acc, off);
            if (lane == 0) xb[bb][p] = tanhf(acc);
        }
    }
    __syncthreads();

    // stage 3: x3 -> global
    for (int p = warp; p < HP; p += 8) {
        float wr[4];
#pragma unroll
        for (int j = 0; j < 4; j++) wr[j] = w3[p * HP + lane + 32 * j];
#pragma unroll
        for (int bb = 0; bb < 8; bb++) {
            float acc = 0.0f;
#pragma unroll
            for (int j = 0; j < 4; j++) acc = fmaf(wr[j], xb[bb][lane + 32 * j], acc);
#pragma unroll
            for (int off = 16; off > 0; off >>= 1)
                acc += __shfl_xor_sync(0xffffffffu, acc, off);
            if (lane == 0) g_x3[(b0 + bb) * HP + p] = tanhf(acc);
        }
    }
}

// ---------------------------------------------------------------------------
// Kernel 2: fused hyper-GEMM + fold.
//   out[b, kk] = fold( sum_h vec[b,h] * (sum_r x3[b,r] * W[(kk*H+h)*HP + r]) )
// Grid: (256 kk, 8 batch-tiles of 128). 512 threads.
// SMEM: sA = x3 tile [128][128] (warp-broadcast reads),
//       sB = W tile  [256][129] (pad 1 -> bank = (col+r) mod 32, conflict-free).
// Thread (row=tid/32, col=tid%32): 8 b-rows (row*8+i), 8 h-cols (col+32m).
// Epilogue: multiply by vec, warp-shuffle reduce over the 32 lanes (= full h).
// ---------------------------------------------------------------------------
#define SMEM_BYTES ((128 * HP + H * (HP + 1)) * sizeof(float))

template <bool APPLY_TANH>
__global__ __launch_bounds__(512, 1) void hyper_gemm_kernel(
    const float* __restrict__ W,     // base of the [H*H, HP] weight half
    const float* __restrict__ vec,   // [B, H] fold vector
    float* __restrict__ outp)        // [B, H]
{
    extern __shared__ float sm[];
    float* sA = sm;                  // [128][HP]
    float* sB = sm + 128 * HP;       // [H][HP+1]

    const int kk  = blockIdx.x;          // output index 0..255
    const int b0  = blockIdx.y * 128;    // batch tile
    const int tid = threadIdx.x;
    const int row = tid >> 5;            // 0..15 (warp id)
    const int col = tid & 31;            // 0..31 (lane)

    // load x3 tile (coalesced float4)
    {
        const float4* gx  = reinterpret_cast<const float4*>(g_x3 + b0 * HP);
        float4*       sA4 = reinterpret_cast<float4*>(sA);
        for (int i = tid; i < 128 * HP / 4; i += 512) sA4[i] = gx[i];
    }
    // load W tile: warp `row` handles rows h = row, row+16, ...
    for (int h = row; h < H; h += 16) {
        const float4 v = *reinterpret_cast<const float4*>(
            W + (size_t)(kk * H + h) * HP + col * 4);
        float* dst = sB + h * (HP + 1) + col * 4;
        dst[0] = v.x; dst[1] = v.y; dst[2] = v.z; dst[3] = v.w;
    }
    __syncthreads();

    float acc[8][8];
#pragma unroll
    for (int i = 0; i < 8; i++)
#pragma unroll
        for (int m = 0; m < 8; m++) acc[i][m] = 0.0f;

    const float* aBase = sA + (row * 8) * HP;
    const float* bBase = sB + col * (HP + 1);

#pragma unroll 4
    for (int r = 0; r < HP; r++) {
        float a[8], bf[8];
#pragma unroll
        for (int i = 0; i < 8; i++) a[i] = aBase[i * HP + r];        // broadcast
#pragma unroll
        for (int m = 0; m < 8; m++) bf[m] = bBase[(32 * m) * (HP + 1) + r];
#pragma unroll
        for (int i = 0; i < 8; i++)
#pragma unroll
            for (int m = 0; m < 8; m++)
                acc[i][m] = fmaf(a[i], bf[m], acc[i][m]);
    }

    // epilogue: fold over h with vec, reduce across the 32 lanes (full h range)
    float part[8];
#pragma unroll
    for (int i = 0; i < 8; i++) part[i] = 0.0f;
#pragma unroll
    for (int m = 0; m < 8; m++) {
        const int h = col + 32 * m;
#pragma unroll
        for (int i = 0; i < 8; i++) {
            const float v = vec[(b0 + row * 8 + i) * H + h];
            part[i] = fmaf(acc[i][m], v, part[i]);
        }
    }
#pragma unroll
    for (int i = 0; i < 8; i++) {
#pragma unroll
        for (int off = 16; off > 0; off >>= 1)
            part[i] += __shfl_xor_sync(0xffffffffu, part[i], off);
    }
    if (col == 0) {
#pragma unroll
        for (int i = 0; i < 8; i++) {
            float v = part[i];
            if (APPLY_TANH) v = tanhf(v);
            outp[(b0 + row * 8 + i) * H + kk] = v;
        }
    }
}

// ---------------------------------------------------------------------------
extern "C" void kernel_launch(void* const* d_in, const int* in_sizes, int n_in,
                              void* d_out, int out_size) {
    const float* h0  = (const float*)d_in[0];
    const float* ht  = (const float*)d_in[1];
    const float* msg = (const float*)d_in[2];
    const float* c   = (const float*)d_in[3];
    const float* fc1 = (const float*)d_in[4];
    const float* fc2 = (const float*)d_in[5];
    const float* fc3 = (const float*)d_in[6];
    const float* fc4 = (const float*)d_in[7];
    float* out = (float*)d_out;

    // opt in to >48KB dynamic smem (idempotent; done every call, capture-safe)
    cudaFuncSetAttribute((const void*)hyper_gemm_kernel<true>,
                         cudaFuncAttributeMaxDynamicSharedMemorySize, (int)SMEM_BYTES);
    cudaFuncSetAttribute((const void*)hyper_gemm_kernel<false>,
                         cudaFuncAttributeMaxDynamicSharedMemorySize, (int)SMEM_BYTES);

    void* p_g1 = nullptr;
    cudaGetSymbolAddress(&p_g1, g_g1);

    // 1) tiny MLP chain -> g_x3
    mlp_head_kernel<<<B_TOTAL / 8, 256>>>(h0, ht, c, fc1, fc2, fc3);

    // 2) phase A: g1_out = tanh(msg . (x3 @ W1^T folded))
    hyper_gemm_kernel<true><<<dim3(H, B_TOTAL / 128), 512, SMEM_BYTES>>>(
        fc4, msg, (float*)p_g1);

    // 3) phase B: out = g1_out . (x3 @ W2^T folded)
    hyper_gemm_kernel<false><<<dim3(H, B_TOTAL / 128), 512, SMEM_BYTES>>>(
        fc4 + (size_t)H * H * HP, (const float*)p_g1, out);
}

// round 12
// speedup vs baseline: 1.0014x; 1.0014x over previous
#include <cuda_runtime.h>
#include <cmath>

#define B_TOTAL 1024
#define H 256
#define HP 128

typedef unsigned long long u64;

// Scratch (allocation-free): intermediate activations
__device__ float g_x3[B_TOTAL * HP];   // 512 KB
__device__ float g_g1[B_TOTAL * H];    // 1 MB

__device__ __forceinline__ u64 ffma2(u64 a, u64 b, u64 c) {
    u64 d;
    asm("fma.rn.f32x2 %0, %1, %2, %3;" : "=l"(d) : "l"(a), "l"(b), "l"(c));
    return d;
}

// ---------------------------------------------------------------------------
// Kernel 1: h = cc*h0 + (1-cc)*ht ; x3 = tanh(fc3 @ tanh(fc2 @ tanh(fc1 @ h)))
// 256 CTAs x 128 threads, 4 batches per CTA. Thread p owns output row p of
// each layer: full dot products in registers, zero shuffles.
// ---------------------------------------------------------------------------
__global__ __launch_bounds__(128) void mlp_head_kernel(
    const float* __restrict__ h0, const float* __restrict__ ht,
    const float* __restrict__ cin,
    const float* __restrict__ w1,   // [HP, H]
    const float* __restrict__ w2,   // [HP, HP]
    const float* __restrict__ w3)   // [HP, HP]
{
    __shared__ float hs[4][H];
    __shared__ float xa[4][HP];
    __shared__ float xb[4][HP];

    const int b0  = blockIdx.x * 4;
    const int tid = threadIdx.x;          // = p, 0..127

    const float cc = fminf(fmaxf(cin[0], 0.0f), 1.0f);

    // blend h into shared (coalesced)
    for (int i = tid; i < 4 * H; i += 128) {
        const int bb = i >> 8;
        const int hh = i & (H - 1);
        const int g  = (b0 + bb) * H + hh;
        hs[bb][hh] = cc * h0[g] + (1.0f - cc) * ht[g];
    }
    __syncthreads();

    // stage 1: xa[bb][p] = tanh( w1[p,:] . hs[bb,:] )
    {
        float acc[4] = {0.f, 0.f, 0.f, 0.f};
        const float4* wrow = reinterpret_cast<const float4*>(w1 + tid * H);
#pragma unroll
        for (int c = 0; c < H / 4; c++) {
            const float4 w = __ldg(wrow + c);
#pragma unroll
            for (int bb = 0; bb < 4; bb++) {
                const float4 hv = *reinterpret_cast<const float4*>(&hs[bb][c * 4]);
                acc[bb] = fmaf(w.x, hv.x,
                          fmaf(w.y, hv.y,
                          fmaf(w.z, hv.z,
                          fmaf(w.w, hv.w, acc[bb]))));
            }
        }
#pragma unroll
        for (int bb = 0; bb < 4; bb++) xa[bb][tid] = tanhf(acc[bb]);
    }
    __syncthreads();

    // stage 2
    {
        float acc[4] = {0.f, 0.f, 0.f, 0.f};
        const float4* wrow = reinterpret_cast<const float4*>(w2 + tid * HP);
#pragma unroll
        for (int c = 0; c < HP / 4; c++) {
            const float4 w = __ldg(wrow + c);
#pragma unroll
            for (int bb = 0; bb < 4; bb++) {
                const float4 hv = *reinterpret_cast<const float4*>(&xa[bb][c * 4]);
                acc[bb] = fmaf(w.x, hv.x,
                          fmaf(w.y, hv.y,
                          fmaf(w.z, hv.z,
                          fmaf(w.w, hv.w, acc[bb]))));
            }
        }
#pragma unroll
        for (int bb = 0; bb < 4; bb++) xb[bb][tid] = tanhf(acc[bb]);
    }
    __syncthreads();

    // stage 3 -> g_x3
    {
        float acc[4] = {0.f, 0.f, 0.f, 0.f};
        const float4* wrow = reinterpret_cast<const float4*>(w3 + tid * HP);
#pragma unroll
        for (int c = 0; c < HP / 4; c++) {
            const float4 w = __ldg(wrow + c);
#pragma unroll
            for (int bb = 0; bb < 4; bb++) {
                const float4 hv = *reinterpret_cast<const float4*>(&xb[bb][c * 4]);
                acc[bb] = fmaf(w.x, hv.x,
                          fmaf(w.y, hv.y,
                          fmaf(w.z, hv.z,
                          fmaf(w.w, hv.w, acc[bb]))));
            }
        }
#pragma unroll
        for (int bb = 0; bb < 4; bb++)
            g_x3[(b0 + bb) * HP + tid] = tanhf(acc[bb]);
    }
}

// ---------------------------------------------------------------------------
// Kernel 2: fused hyper-GEMM + fold, f32x2-packed FMA (FFMA2, full dual rate).
//   out[b, kk] = fold( sum_h vec[b,h] * (sum_r x3[b,r] * W[(kk*H+h)*HP + r]) )
// Grid (256 kk, 16 batch-tiles of 64). 512 threads.
// Thread layout: col = tid&31, half = (tid>>5)&1, rowg = tid>>6 (0..7).
//   owns b-rows rowg*8+i (i<8), h-cols = col + 32*m + 128*half (m<4).
// acc[i][m] is a packed f32x2 pair: (sum over even r, sum over odd r).
// sB stride 132 floats -> conflict-free 128-bit LDS (4*col covers all banks).
// ---------------------------------------------------------------------------
#define SB_STRIDE (HP + 4)   // 132
#define SMEM_BYTES ((64 * HP + H * SB_STRIDE) * sizeof(float))

template <bool APPLY_TANH>
__global__ __launch_bounds__(512, 1) void hyper_gemm_kernel(
    const float* __restrict__ W,     // base of the [H*H, HP] weight half
    const float* __restrict__ vec,   // [B, H] fold vector
    float* __restrict__ outp)        // [B, H]
{
    extern __shared__ float sm[];
    float* sA = sm;                  // [64][HP]
    float* sB = sm + 64 * HP;        // [H][SB_STRIDE]
    __shared__ float red[8][8];      // cross-half exchange

    const int kk   = blockIdx.x;         // output index 0..255
    const int b0   = blockIdx.y * 64;    // batch tile
    const int tid  = threadIdx.x;
    const int col  = tid & 31;
    const int half = (tid >> 5) & 1;
    const int rowg = tid >> 6;           // 0..7

    // load x3 tile [64][128] (coalesced float4)
    {
        const float4* gx  = reinterpret_cast<const float4*>(g_x3 + b0 * HP);
        float4*       sA4 = reinterpret_cast<float4*>(sA);
        for (int i = tid; i < 64 * HP / 4; i += 512) sA4[i] = gx[i];
    }
    // load W tile [256][128] into padded sB (coalesced float4 in, bank-clean out)
    for (int idx = tid; idx < H * (HP / 4); idx += 512) {
        const int h  = idx >> 5;         // row
        const int c4 = idx & 31;         // float4 within row
        const float4 v = __ldg(reinterpret_cast<const float4*>(
            W + (size_t)(kk * H + h) * HP) + c4);
        *reinterpret_cast<float4*>(sB + h * SB_STRIDE + c4 * 4) = v;
    }
    __syncthreads();

    u64 acc[8][4];
#pragma unroll
    for (int i = 0; i < 8; i++)
#pragma unroll
        for (int m = 0; m < 4; m++) acc[i][m] = 0ull;

    const float* aBase = sA + (rowg * 8) * HP;
    const float* bBase = sB + (col + 128 * half) * SB_STRIDE;

    for (int r = 0; r < HP; r += 4) {
        ulonglong2 b[4];
#pragma unroll
        for (int m = 0; m < 4; m++)
            b[m] = *reinterpret_cast<const ulonglong2*>(bBase + m * 32 * SB_STRIDE + r);
#pragma unroll
        for (int i = 0; i < 8; i++) {
            const ulonglong2 a = *reinterpret_cast<const ulonglong2*>(aBase + i * HP + r);
#pragma unroll
            for (int m = 0; m < 4; m++) {
                acc[i][m] = ffma2(a.x, b[m].x, acc[i][m]);
                acc[i][m] = ffma2(a.y, b[m].y, acc[i][m]);
            }
        }
    }

    // epilogue: unpack pairs, fold with vec over this thread's 4 h's,
    // shuffle-reduce over 32 lanes (=128 h's per half), combine halves.
    float part[8];
#pragma unroll
    for (int i = 0; i < 8; i++) part[i] = 0.0f;
#pragma unroll
    for (int m = 0; m < 4; m++) {
        const int h = col + 32 * m + 128 * half;
#pragma unroll
        for (int i = 0; i < 8; i++) {
            const float2 p = *reinterpret_cast<const float2*>(&acc[i][m]);
            const float s = p.x + p.y;
            const float v = vec[(size_t)(b0 + rowg * 8 + i) * H + h];
            part[i] = fmaf(s, v, part[i]);
        }
    }
#pragma unroll
    for (int i = 0; i < 8; i++) {
#pragma unroll
        for (int off = 16; off > 0; off >>= 1)
            part[i] += __shfl_xor_sync(0xffffffffu, part[i], off);
    }
    // after xor-reduce every lane holds the half-sum for all i
    if (half == 1) {
#pragma unroll
        for (int i = 0; i < 8; i++)
            if (col == i) red[rowg][i] = part[i];
    }
    __syncthreads();
    if (half == 0) {
#pragma unroll
        for (int i = 0; i < 8; i++) {
            if (col == i) {
                float v = part[i] + red[rowg][i];
                if (APPLY_TANH) v = tanhf(v);
                outp[(size_t)(b0 + rowg * 8 + i) * H + kk] = v;
            }
        }
    }
}

// ---------------------------------------------------------------------------
extern "C" void kernel_launch(void* const* d_in, const int* in_sizes, int n_in,
                              void* d_out, int out_size) {
    const float* h0  = (const float*)d_in[0];
    const float* ht  = (const float*)d_in[1];
    const float* msg = (const float*)d_in[2];
    const float* c   = (const float*)d_in[3];
    const float* fc1 = (const float*)d_in[4];
    const float* fc2 = (const float*)d_in[5];
    const float* fc3 = (const float*)d_in[6];
    const float* fc4 = (const float*)d_in[7];
    float* out = (float*)d_out;

    cudaFuncSetAttribute((const void*)hyper_gemm_kernel<true>,
                         cudaFuncAttributeMaxDynamicSharedMemorySize, (int)SMEM_BYTES);
    cudaFuncSetAttribute((const void*)hyper_gemm_kernel<false>,
                         cudaFuncAttributeMaxDynamicSharedMemorySize, (int)SMEM_BYTES);

    void* p_g1 = nullptr;
    cudaGetSymbolAddress(&p_g1, g_g1);

    // 1) tiny MLP chain -> g_x3
    mlp_head_kernel<<<B_TOTAL / 4, 128>>>(h0, ht, c, fc1, fc2, fc3);

    // 2) phase A: g1 = tanh( fold(msg, x3 @ W1^T) )
    hyper_gemm_kernel<true><<<dim3(H, B_TOTAL / 64), 512, SMEM_BYTES>>>(
        fc4, msg, (float*)p_g1);

    // 3) phase B: out = fold(g1, x3 @ W2^T)
    hyper_gemm_kernel<false><<<dim3(H, B_TOTAL / 64), 512, SMEM_BYTES>>>(
        fc4 + (size_t)H * H * HP, (const float*)p_g1, out);
}

// round 14
// speedup vs baseline: 1.3354x; 1.3335x over previous
#include <cuda_runtime.h>
#include <cuda_bf16.h>
#include <cstdint>
#include <cmath>

#define B_TOTAL 1024
#define H 256
#define HP 128

typedef unsigned int u32;

// ---------------------------------------------------------------------------
// Scratch (static device arrays — allocation-free)
// ---------------------------------------------------------------------------
__device__ __nv_bfloat16 g_x3h[B_TOTAL * HP];          // 256 KB
__device__ __nv_bfloat16 g_x3l[B_TOTAL * HP];          // 256 KB
__device__ __nv_bfloat16 g_Wh[2 * H * H * HP];         // 33.5 MB
__device__ __nv_bfloat16 g_Wl[2 * H * H * HP];         // 33.5 MB
__device__ float         g_g1[B_TOTAL * H];            // 1 MB

__device__ __forceinline__ u32 smem_u32_of(const void* p) {
    u32 a;
    asm("{ .reg .u64 t; cvta.to.shared.u64 t, %1; cvt.u32.u64 %0, t; }"
        : "=r"(a) : "l"(p));
    return a;
}

__device__ __forceinline__ void ldsm4(u32* r, u32 addr) {
    asm volatile("ldmatrix.sync.aligned.m8n8.x4.shared.b16 {%0,%1,%2,%3}, [%4];"
                 : "=r"(r[0]), "=r"(r[1]), "=r"(r[2]), "=r"(r[3]) : "r"(addr));
}

__device__ __forceinline__ void mma_bf16(float* c, const u32* a, const u32* b) {
    asm volatile(
        "mma.sync.aligned.m16n8k16.row.col.f32.bf16.bf16.f32 "
        "{%0,%1,%2,%3}, {%4,%5,%6,%7}, {%8,%9}, {%0,%1,%2,%3};"
        : "+f"(c[0]), "+f"(c[1]), "+f"(c[2]), "+f"(c[3])
        : "r"(a[0]), "r"(a[1]), "r"(a[2]), "r"(a[3]), "r"(b[0]), "r"(b[1]));
}

// ---------------------------------------------------------------------------
// Kernel 0: split fc4 fp32 -> bf16 hi + bf16 lo
// ---------------------------------------------------------------------------
__global__ __launch_bounds__(256) void wsplit_kernel(const float* __restrict__ w) {
    const size_t n4 = (size_t)2 * H * H * HP / 4;
    __nv_bfloat162* wh = reinterpret_cast<__nv_bfloat162*>(g_Wh);
    __nv_bfloat162* wl = reinterpret_cast<__nv_bfloat162*>(g_Wl);
    for (size_t i = (size_t)blockIdx.x * blockDim.x + threadIdx.x; i < n4;
         i += (size_t)gridDim.x * blockDim.x) {
        const float4 v = __ldg(reinterpret_cast<const float4*>(w) + i);
        __nv_bfloat16 hx = __float2bfloat16(v.x), hy = __float2bfloat16(v.y);
        __nv_bfloat16 hz = __float2bfloat16(v.z), hw = __float2bfloat16(v.w);
        __nv_bfloat16 lx = __float2bfloat16(v.x - __bfloat162float(hx));
        __nv_bfloat16 ly = __float2bfloat16(v.y - __bfloat162float(hy));
        __nv_bfloat16 lz = __float2bfloat16(v.z - __bfloat162float(hz));
        __nv_bfloat16 lw = __float2bfloat16(v.w - __bfloat162float(hw));
        wh[2 * i]     = __nv_bfloat162(hx, hy);
        wh[2 * i + 1] = __nv_bfloat162(hz, hw);
        wl[2 * i]     = __nv_bfloat162(lx, ly);
        wl[2 * i + 1] = __nv_bfloat162(lz, lw);
    }
}

// ---------------------------------------------------------------------------
// Kernel 1: MLP head -> x3 split hi/lo bf16
// ---------------------------------------------------------------------------
__global__ __launch_bounds__(128) void mlp_head_kernel(
    const float* __restrict__ h0, const float* __restrict__ ht,
    const float* __restrict__ cin,
    const float* __restrict__ w1, const float* __restrict__ w2,
    const float* __restrict__ w3)
{
    __shared__ float hs[4][H];
    __shared__ float xa[4][HP];
    __shared__ float xb[4][HP];

    const int b0  = blockIdx.x * 4;
    const int tid = threadIdx.x;
    const float cc = fminf(fmaxf(cin[0], 0.0f), 1.0f);

    for (int i = tid; i < 4 * H; i += 128) {
        const int bb = i >> 8, hh = i & (H - 1);
        const int g = (b0 + bb) * H + hh;
        hs[bb][hh] = cc * h0[g] + (1.0f - cc) * ht[g];
    }
    __syncthreads();

    {
        float acc[4] = {0.f, 0.f, 0.f, 0.f};
        const float4* wrow = reinterpret_cast<const float4*>(w1 + tid * H);
#pragma unroll
        for (int c = 0; c < H / 4; c++) {
            const float4 w = __ldg(wrow + c);
#pragma unroll
            for (int bb = 0; bb < 4; bb++) {
                const float4 hv = *reinterpret_cast<const float4*>(&hs[bb][c * 4]);
                acc[bb] = fmaf(w.x, hv.x, fmaf(w.y, hv.y,
                          fmaf(w.z, hv.z, fmaf(w.w, hv.w, acc[bb]))));
            }
        }
#pragma unroll
        for (int bb = 0; bb < 4; bb++) xa[bb][tid] = tanhf(acc[bb]);
    }
    __syncthreads();
    {
        float acc[4] = {0.f, 0.f, 0.f, 0.f};
        const float4* wrow = reinterpret_cast<const float4*>(w2 + tid * HP);
#pragma unroll
        for (int c = 0; c < HP / 4; c++) {
            const float4 w = __ldg(wrow + c);
#pragma unroll
            for (int bb = 0; bb < 4; bb++) {
                const float4 hv = *reinterpret_cast<const float4*>(&xa[bb][c * 4]);
                acc[bb] = fmaf(w.x, hv.x, fmaf(w.y, hv.y,
                          fmaf(w.z, hv.z, fmaf(w.w, hv.w, acc[bb]))));
            }
        }
#pragma unroll
        for (int bb = 0; bb < 4; bb++) xb[bb][tid] = tanhf(acc[bb]);
    }
    __syncthreads();
    {
        float acc[4] = {0.f, 0.f, 0.f, 0.f};
        const float4* wrow = reinterpret_cast<const float4*>(w3 + tid * HP);
#pragma unroll
        for (int c = 0; c < HP / 4; c++) {
            const float4 w = __ldg(wrow + c);
#pragma unroll
            for (int bb = 0; bb < 4; bb++) {
                const float4 hv = *reinterpret_cast<const float4*>(&xb[bb][c * 4]);
                acc[bb] = fmaf(w.x, hv.x, fmaf(w.y, hv.y,
                          fmaf(w.z, hv.z, fmaf(w.w, hv.w, acc[bb]))));
            }
        }
#pragma unroll
        for (int bb = 0; bb < 4; bb++) {
            const float v = tanhf(acc[bb]);
            const __nv_bfloat16 hv = __float2bfloat16(v);
            const int o = (b0 + bb) * HP + tid;
            g_x3h[o] = hv;
            g_x3l[o] = __float2bfloat16(v - __bfloat162float(hv));
        }
    }
}

// ---------------------------------------------------------------------------
// Kernel 2: HMMA (mma.sync bf16) hyper-GEMM + fold, bf16x3 split precision.
// Per CTA: D[128b x 256h] = x3[128x128] @ W_kk[256x128]^T; fold with vec.
// Smem tiles row-major, 272-byte stride (17 granules -> ldmatrix conflict-free).
// Warp (bgrp=wid&3, hgrp=wid>>2) owns 32b x 64h: acc[2][8][4].
// ---------------------------------------------------------------------------
#define TSTRIDE 272                 // bytes per tile row (128 bf16 + pad)
#define OFF_AH  0
#define OFF_AL  (128 * TSTRIDE)                 // 34816
#define OFF_BH  (2 * 128 * TSTRIDE)             // 69632
#define OFF_BL  (OFF_BH + 256 * TSTRIDE)        // 139264
#define OFF_RED (OFF_BL + 256 * TSTRIDE)        // 208896
#define SMEM_TOTAL (OFF_RED + 128 * 4 * 4)      // 210944 bytes

template <bool APPLY_TANH>
__global__ __launch_bounds__(512, 1) void hyper_mma_kernel(
    const __nv_bfloat16* __restrict__ Wh,   // phase half, [H*H, HP]
    const __nv_bfloat16* __restrict__ Wl,
    const float* __restrict__ vec,          // [B, H]
    float* __restrict__ outp)               // [B, H]
{
    extern __shared__ __align__(16) char smem[];
    const u32 smb = smem_u32_of(smem);
    float* red = reinterpret_cast<float*>(smem + OFF_RED);   // [128][4]

    const int kk   = blockIdx.x;
    const int b0   = blockIdx.y * 128;
    const int tid  = threadIdx.x;
    const int wid  = tid >> 5;
    const int lane = tid & 31;

    // ---- load A tiles (x3 hi/lo): 128 rows x 16 uint4 ----
    for (int idx = tid; idx < 128 * 16; idx += 512) {
        const int row = idx >> 4, c = idx & 15;
        const size_t src = (size_t)(b0 + row) * HP + c * 8;
        const int dst = row * TSTRIDE + c * 16;
        *reinterpret_cast<uint4*>(smem + OFF_AH + dst) =
            __ldg(reinterpret_cast<const uint4*>(g_x3h + src));
        *reinterpret_cast<uint4*>(smem + OFF_AL + dst) =
            __ldg(reinterpret_cast<const uint4*>(g_x3l + src));
    }
    // ---- load B tiles (W hi/lo): 256 rows x 16 uint4 ----
    const size_t wbase = (size_t)kk * H * HP;
    for (int idx = tid; idx < 256 * 16; idx += 512) {
        const int row = idx >> 4, c = idx & 15;
        const size_t src = wbase + (size_t)row * HP + c * 8;
        const int dst = row * TSTRIDE + c * 16;
        *reinterpret_cast<uint4*>(smem + OFF_BH + dst) =
            __ldg(reinterpret_cast<const uint4*>(Wh + src));
        *reinterpret_cast<uint4*>(smem + OFF_BL + dst) =
            __ldg(reinterpret_cast<const uint4*>(Wl + src));
    }
    __syncthreads();

    const int bgrp = wid & 3;     // batch 32-row group
    const int hgrp = wid >> 2;    // h 64-col group

    float acc[2][8][4];
#pragma unroll
    for (int t = 0; t < 2; t++)
#pragma unroll
        for (int j = 0; j < 8; j++)
#pragma unroll
            for (int e = 0; e < 4; e++) acc[t][j][e] = 0.0f;

    // per-lane ldmatrix address offsets (within a tile)
    const u32 aAddr = (u32)((bgrp * 32 + (lane & 15)) * TSTRIDE + (lane >> 4) * 16);
    const u32 bAddr = (u32)((hgrp * 64 + ((lane >> 4) << 3) + (lane & 7)) * TSTRIDE
                            + (((lane >> 3) & 1) * 16));

    // products: A_hi*B_hi, A_hi*B_lo, A_lo*B_hi
    const u32 aOffs[3] = {smb + OFF_AH, smb + OFF_AH, smb + OFF_AL};
    const u32 bOffs[3] = {smb + OFF_BH, smb + OFF_BL, smb + OFF_BH};

#pragma unroll
    for (int p = 0; p < 3; p++) {
        const u32 aBase = aOffs[p] + aAddr;
        const u32 bBase = bOffs[p] + bAddr;
#pragma unroll
        for (int k = 0; k < 8; k++) {
            const u32 koff = k * 32;   // 16 bf16 per k-step
            u32 a0[4], a1[4];
            ldsm4(a0, aBase + koff);
            ldsm4(a1, aBase + 16 * TSTRIDE + koff);
#pragma unroll
            for (int jp = 0; jp < 4; jp++) {
                u32 bb[4];
                ldsm4(bb, bBase + jp * 16 * TSTRIDE + koff);
                mma_bf16(acc[0][2 * jp],     a0, bb);
                mma_bf16(acc[0][2 * jp + 1], a0, bb + 2);
                mma_bf16(acc[1][2 * jp],     a1, bb);
                mma_bf16(acc[1][2 * jp + 1], a1, bb + 2);
            }
        }
    }

    // ---- epilogue: fold with vec, reduce ----
    const int gid = lane >> 2;          // 0..7 row group
    const int cp  = (lane & 3) * 2;     // col pair base
#pragma unroll
    for (int t = 0; t < 2; t++) {
        const int rowA = bgrp * 32 + t * 16 + gid;
        const int rowB = rowA + 8;
        const float* vA = vec + (size_t)(b0 + rowA) * H + hgrp * 64 + cp;
        const float* vB = vec + (size_t)(b0 + rowB) * H + hgrp * 64 + cp;
        float pA = 0.f, pB = 0.f;
#pragma unroll
        for (int j = 0; j < 8; j++) {
            const float2 a2 = __ldg(reinterpret_cast<const float2*>(vA + j * 8));
            const float2 b2 = __ldg(reinterpret_cast<const float2*>(vB + j * 8));
            pA = fmaf(acc[t][j][0], a2.x, fmaf(acc[t][j][1], a2.y, pA));
            pB = fmaf(acc[t][j][2], b2.x, fmaf(acc[t][j][3], b2.y, pB));
        }
        pA += __shfl_xor_sync(0xffffffffu, pA, 1);
        pA += __shfl_xor_sync(0xffffffffu, pA, 2);
        pB += __shfl_xor_sync(0xffffffffu, pB, 1);
        pB += __shfl_xor_sync(0xffffffffu, pB, 2);
        if ((lane & 3) == 0) {
            red[(bgrp * 32 + t * 16 + gid) * 4 + hgrp] = pA;
            red[(bgrp * 32 + t * 16 + gid + 8) * 4 + hgrp] = pB;
        }
    }
    __syncthreads();

    if (tid < 128) {
        float s = red[tid * 4 + 0] + red[tid * 4 + 1]
                + red[tid * 4 + 2] + red[tid * 4 + 3];
        if (APPLY_TANH) s = tanhf(s);
        outp[(size_t)(b0 + tid) * H + kk] = s;
    }
}

// ---------------------------------------------------------------------------
extern "C" void kernel_launch(void* const* d_in, const int* in_sizes, int n_in,
                              void* d_out, int out_size) {
    const float* h0  = (const float*)d_in[0];
    const float* ht  = (const float*)d_in[1];
    const float* msg = (const float*)d_in[2];
    const float* c   = (const float*)d_in[3];
    const float* fc1 = (const float*)d_in[4];
    const float* fc2 = (const float*)d_in[5];
    const float* fc3 = (const float*)d_in[6];
    const float* fc4 = (const float*)d_in[7];
    float* out = (float*)d_out;

    cudaFuncSetAttribute((const void*)hyper_mma_kernel<true>,
                         cudaFuncAttributeMaxDynamicSharedMemorySize, SMEM_TOTAL);
    cudaFuncSetAttribute((const void*)hyper_mma_kernel<false>,
                         cudaFuncAttributeMaxDynamicSharedMemorySize, SMEM_TOTAL);

    void* p_g1 = nullptr;
    cudaGetSymbolAddress(&p_g1, g_g1);
    void* p_wh = nullptr;
    cudaGetSymbolAddress(&p_wh, g_Wh);
    void* p_wl = nullptr;
    cudaGetSymbolAddress(&p_wl, g_Wl);

    const size_t half = (size_t)H * H * HP;   // elements per phase half

    // 0) split fc4 into bf16 hi/lo
    wsplit_kernel<<<2048, 256>>>(fc4);

    // 1) MLP head -> x3 hi/lo
    mlp_head_kernel<<<B_TOTAL / 4, 128>>>(h0, ht, c, fc1, fc2, fc3);

    // 2) phase A: g1 = tanh( fold(msg, x3 @ W1^T) )
    hyper_mma_kernel<true><<<dim3(H, B_TOTAL / 128), 512, SMEM_TOTAL>>>(
        (const __nv_bfloat16*)p_wh, (const __nv_bfloat16*)p_wl,
        msg, (float*)p_g1);

    // 3) phase B: out = fold(g1, x3 @ W2^T)
    hyper_mma_kernel<false><<<dim3(H, B_TOTAL / 128), 512, SMEM_TOTAL>>>(
        (const __nv_bfloat16*)p_wh + half, (const __nv_bfloat16*)p_wl + half,
        (const float*)p_g1, out);
}

// round 15
// speedup vs baseline: 2.7296x; 2.0440x over previous
#include <cuda_runtime.h>
#include <cuda_bf16.h>
#include <cstdint>
#include <cmath>

#define B_TOTAL 1024
#define H 256
#define HP 128

typedef unsigned int u32;

// ---------------------------------------------------------------------------
// Scratch (static device arrays — allocation-free)
// ---------------------------------------------------------------------------
__device__ __nv_bfloat16 g_x3h[B_TOTAL * HP];          // 256 KB
__device__ __nv_bfloat16 g_x3l[B_TOTAL * HP];          // 256 KB
__device__ float         g_g1[B_TOTAL * H];            // 1 MB

__device__ __forceinline__ u32 smem_u32_of(const void* p) {
    u32 a;
    asm("{ .reg .u64 t; cvta.to.shared.u64 t, %1; cvt.u32.u64 %0, t; }"
        : "=r"(a) : "l"(p));
    return a;
}

__device__ __forceinline__ void ldsm4(u32* r, u32 addr) {
    asm volatile("ldmatrix.sync.aligned.m8n8.x4.shared.b16 {%0,%1,%2,%3}, [%4];"
                 : "=r"(r[0]), "=r"(r[1]), "=r"(r[2]), "=r"(r[3]) : "r"(addr));
}

__device__ __forceinline__ void mma_bf16(float* c, const u32* a, const u32* b) {
    asm volatile(
        "mma.sync.aligned.m16n8k16.row.col.f32.bf16.bf16.f32 "
        "{%0,%1,%2,%3}, {%4,%5,%6,%7}, {%8,%9}, {%0,%1,%2,%3};"
        : "+f"(c[0]), "+f"(c[1]), "+f"(c[2]), "+f"(c[3])
        : "r"(a[0]), "r"(a[1]), "r"(a[2]), "r"(a[3]), "r"(b[0]), "r"(b[1]));
}

__device__ __forceinline__ void cp16(u32 dst, const void* src) {
    const size_t gs = __cvta_generic_to_global(src);
    asm volatile("cp.async.ca.shared.global [%0], [%1], 16;"
                 :: "r"(dst), "l"(gs) : "memory");
}
#define CP_COMMIT() asm volatile("cp.async.commit_group;" ::: "memory")
#define CP_WAIT(n)  asm volatile("cp.async.wait_group %0;" :: "n"(n) : "memory")

__device__ __forceinline__ u32 pack_bf16x2(__nv_bfloat16 a, __nv_bfloat16 b) {
    __nv_bfloat162 t(a, b);
    return *reinterpret_cast<u32*>(&t);
}

// ---------------------------------------------------------------------------
// Kernel 1: MLP head -> x3 split hi/lo bf16 (unchanged, 26us)
// ---------------------------------------------------------------------------
__global__ __launch_bounds__(128) void mlp_head_kernel(
    const float* __restrict__ h0, const float* __restrict__ ht,
    const float* __restrict__ cin,
    const float* __restrict__ w1, const float* __restrict__ w2,
    const float* __restrict__ w3)
{
    __shared__ float hs[4][H];
    __shared__ float xa[4][HP];
    __shared__ float xb[4][HP];

    const int b0  = blockIdx.x * 4;
    const int tid = threadIdx.x;
    const float cc = fminf(fmaxf(cin[0], 0.0f), 1.0f);

    for (int i = tid; i < 4 * H; i += 128) {
        const int bb = i >> 8, hh = i & (H - 1);
        const int g = (b0 + bb) * H + hh;
        hs[bb][hh] = cc * h0[g] + (1.0f - cc) * ht[g];
    }
    __syncthreads();

    {
        float acc[4] = {0.f, 0.f, 0.f, 0.f};
        const float4* wrow = reinterpret_cast<const float4*>(w1 + tid * H);
#pragma unroll
        for (int c = 0; c < H / 4; c++) {
            const float4 w = __ldg(wrow + c);
#pragma unroll
            for (int bb = 0; bb < 4; bb++) {
                const float4 hv = *reinterpret_cast<const float4*>(&hs[bb][c * 4]);
                acc[bb] = fmaf(w.x, hv.x, fmaf(w.y, hv.y,
                          fmaf(w.z, hv.z, fmaf(w.w, hv.w, acc[bb]))));
            }
        }
#pragma unroll
        for (int bb = 0; bb < 4; bb++) xa[bb][tid] = tanhf(acc[bb]);
    }
    __syncthreads();
    {
        float acc[4] = {0.f, 0.f, 0.f, 0.f};
        const float4* wrow = reinterpret_cast<const float4*>(w2 + tid * HP);
#pragma unroll
        for (int c = 0; c < HP / 4; c++) {
            const float4 w = __ldg(wrow + c);
#pragma unroll
            for (int bb = 0; bb < 4; bb++) {
                const float4 hv = *reinterpret_cast<const float4*>(&xa[bb][c * 4]);
                acc[bb] = fmaf(w.x, hv.x, fmaf(w.y, hv.y,
                          fmaf(w.z, hv.z, fmaf(w.w, hv.w, acc[bb]))));
            }
        }
#pragma unroll
        for (int bb = 0; bb < 4; bb++) xb[bb][tid] = tanhf(acc[bb]);
    }
    __syncthreads();
    {
        float acc[4] = {0.f, 0.f, 0.f, 0.f};
        const float4* wrow = reinterpret_cast<const float4*>(w3 + tid * HP);
#pragma unroll
        for (int c = 0; c < HP / 4; c++) {
            const float4 w = __ldg(wrow + c);
#pragma unroll
            for (int bb = 0; bb < 4; bb++) {
                const float4 hv = *reinterpret_cast<const float4*>(&xb[bb][c * 4]);
                acc[bb] = fmaf(w.x, hv.x, fmaf(w.y, hv.y,
                          fmaf(w.z, hv.z, fmaf(w.w, hv.w, acc[bb]))));
            }
        }
#pragma unroll
        for (int bb = 0; bb < 4; bb++) {
            const float v = tanhf(acc[bb]);
            const __nv_bfloat16 hv = __float2bfloat16(v);
            const int o = (b0 + bb) * HP + tid;
            g_x3h[o] = hv;
            g_x3l[o] = __float2bfloat16(v - __bfloat162float(hv));
        }
    }
}

// ---------------------------------------------------------------------------
// Kernel 2: W-resident HMMA hyper-GEMM + fold, bf16x3 split precision.
// One CTA per kk (grid 256, 256 threads / 8 warps). The CTA:
//   - loads its W_kk tile [256h x 128r] as fp32 ONCE, splits to bf16 hi/lo smem
//   - loops over 16 b-tiles of 64 rows: cp.async double-buffered A (x3 hi/lo),
//     D[64b x 256h] = x3 . W^T via 3 split HMMA products, folds with vec -> out
// Warp (bgrp=wid&1, hgrp=wid>>1) owns 32b x 64h: acc[2][8][4] (64 regs).
// ---------------------------------------------------------------------------
#define TSTRIDE 272                 // bytes per tile row (128 bf16 + pad)
#define OFF_BH  0
#define OFF_BL  (256 * TSTRIDE)                 // 69632
#define OFF_AST (2 * 256 * TSTRIDE)             // 139264
#define A_STAGE (2 * 64 * TSTRIDE)              // 34816 (hi+lo)
#define OFF_RED (OFF_AST + 2 * A_STAGE)         // 208896
#define SMEM_TOTAL (OFF_RED + 64 * 4 * 4)       // 209920 bytes
#define NIT 16

template <bool APPLY_TANH>
__global__ __launch_bounds__(256, 1) void hyper_mma_kernel(
    const float* __restrict__ W,     // phase half, fp32 [H*H, HP]
    const float* __restrict__ vec,   // [B, H]
    float* __restrict__ outp)        // [B, H]
{
    extern __shared__ __align__(16) char smem[];
    const u32 smb = smem_u32_of(smem);
    float* red = reinterpret_cast<float*>(smem + OFF_RED);   // [64][4]

    const int kk   = blockIdx.x;
    const int tid  = threadIdx.x;
    const int wid  = tid >> 5;
    const int lane = tid & 31;

    // ---- one-time: load W_kk fp32, split to bf16 hi/lo tiles ----
    {
        const float4* Wp = reinterpret_cast<const float4*>(W + (size_t)kk * H * HP);
        for (int i = tid; i < H * 32; i += 256) {      // 256 rows x 32 float4
            const int row = i >> 5, c4 = i & 31;
            const float4 v = __ldg(Wp + i);
            const __nv_bfloat16 hx = __float2bfloat16(v.x);
            const __nv_bfloat16 hy = __float2bfloat16(v.y);
            const __nv_bfloat16 hz = __float2bfloat16(v.z);
            const __nv_bfloat16 hw = __float2bfloat16(v.w);
            uint2 hp, lp;
            hp.x = pack_bf16x2(hx, hy);
            hp.y = pack_bf16x2(hz, hw);
            lp.x = pack_bf16x2(__float2bfloat16(v.x - __bfloat162float(hx)),
                               __float2bfloat16(v.y - __bfloat162float(hy)));
            lp.y = pack_bf16x2(__float2bfloat16(v.z - __bfloat162float(hz)),
                               __float2bfloat16(v.w - __bfloat162float(hw)));
            const int dst = row * TSTRIDE + c4 * 8;
            *reinterpret_cast<uint2*>(smem + OFF_BH + dst) = hp;
            *reinterpret_cast<uint2*>(smem + OFF_BL + dst) = lp;
        }
    }

    // ---- A prefetch lambda (cp.async, 64 rows x 16 granules, hi+lo) ----
    auto prefetch = [&](int it) {
        const int s = it & 1;
        const u32 aHi = smb + OFF_AST + s * A_STAGE;
        const u32 aLo = aHi + 64 * TSTRIDE;
        const size_t base = (size_t)it * 64 * HP;
        for (int i = tid; i < 64 * 16; i += 256) {
            const int row = i >> 4, g = i & 15;
            const size_t src = base + (size_t)row * HP + g * 8;
            const u32 d = row * TSTRIDE + g * 16;
            cp16(aHi + d, g_x3h + src);
            cp16(aLo + d, g_x3l + src);
        }
    };

    prefetch(0);
    CP_COMMIT();

    const int bgrp = wid & 1;     // 32-row group within the 64-row tile
    const int hgrp = wid >> 1;    // 64-col h group

    // per-lane ldmatrix offsets
    const u32 aOff = (u32)((bgrp * 32 + (lane & 15)) * TSTRIDE + (lane >> 4) * 16);
    const u32 bBase = smb +
        (u32)((hgrp * 64 + ((lane >> 4) << 3) + (lane & 7)) * TSTRIDE
              + (((lane >> 3) & 1) * 16));

    const int gid = lane >> 2;          // 0..7
    const int cp  = (lane & 3) * 2;     // col pair base

    for (int it = 0; it < NIT; it++) {
        if (it + 1 < NIT) {
            prefetch(it + 1);
            CP_COMMIT();
            CP_WAIT(1);
        } else {
            CP_WAIT(0);
        }
        __syncthreads();

        const int s = it & 1;
        const u32 aHi = smb + OFF_AST + s * A_STAGE + aOff;
        const u32 aLo = aHi + 64 * TSTRIDE;

        float acc[2][8][4];
#pragma unroll
        for (int t = 0; t < 2; t++)
#pragma unroll
            for (int j = 0; j < 8; j++)
#pragma unroll
                for (int e = 0; e < 4; e++) acc[t][j][e] = 0.0f;

#pragma unroll
        for (int k = 0; k < 8; k++) {
            const u32 koff = k * 32;
            u32 ah0[4], ah1[4], al0[4], al1[4];
            ldsm4(ah0, aHi + koff);
            ldsm4(ah1, aHi + 16 * TSTRIDE + koff);
            ldsm4(al0, aLo + koff);
            ldsm4(al1, aLo + 16 * TSTRIDE + koff);
#pragma unroll
            for (int jp = 0; jp < 4; jp++) {
                u32 bh[4], bl[4];
                ldsm4(bh, bBase + OFF_BH + jp * 16 * TSTRIDE + koff);
                ldsm4(bl, bBase + OFF_BL + jp * 16 * TSTRIDE + koff);
                // product 1: A_hi * B_hi
                mma_bf16(acc[0][2 * jp],     ah0, bh);
                mma_bf16(acc[0][2 * jp + 1], ah0, bh + 2);
                mma_bf16(acc[1][2 * jp],     ah1, bh);
                mma_bf16(acc[1][2 * jp + 1], ah1, bh + 2);
                // product 2: A_hi * B_lo
                mma_bf16(acc[0][2 * jp],     ah0, bl);
                mma_bf16(acc[0][2 * jp + 1], ah0, bl + 2);
                mma_bf16(acc[1][2 * jp],     ah1, bl);
                mma_bf16(acc[1][2 * jp + 1], ah1, bl + 2);
                // product 3: A_lo * B_hi
                mma_bf16(acc[0][2 * jp],     al0, bh);
                mma_bf16(acc[0][2 * jp + 1], al0, bh + 2);
                mma_bf16(acc[1][2 * jp],     al1, bh);
                mma_bf16(acc[1][2 * jp + 1], al1, bh + 2);
            }
        }

        // ---- epilogue: fold with vec, reduce over h ----
        const int b0 = it * 64;
#pragma unroll
        for (int t = 0; t < 2; t++) {
            const int rowA = bgrp * 32 + t * 16 + gid;
            const int rowB = rowA + 8;
            const float* vA = vec + (size_t)(b0 + rowA) * H + hgrp * 64 + cp;
            const float* vB = vec + (size_t)(b0 + rowB) * H + hgrp * 64 + cp;
            float pA = 0.f, pB = 0.f;
#pragma unroll
            for (int j = 0; j < 8; j++) {
                const float2 a2 = __ldg(reinterpret_cast<const float2*>(vA + j * 8));
                const float2 b2 = __ldg(reinterpret_cast<const float2*>(vB + j * 8));
                pA = fmaf(acc[t][j][0], a2.x, fmaf(acc[t][j][1], a2.y, pA));
                pB = fmaf(acc[t][j][2], b2.x, fmaf(acc[t][j][3], b2.y, pB));
            }
            pA += __shfl_xor_sync(0xffffffffu, pA, 1);
            pA += __shfl_xor_sync(0xffffffffu, pA, 2);
            pB += __shfl_xor_sync(0xffffffffu, pB, 1);
            pB += __shfl_xor_sync(0xffffffffu, pB, 2);
            if ((lane & 3) == 0) {
                red[rowA * 4 + hgrp] = pA;
                red[rowB * 4 + hgrp] = pB;
            }
        }
        __syncthreads();

        if (tid < 64) {
            float sv = red[tid * 4 + 0] + red[tid * 4 + 1]
                     + red[tid * 4 + 2] + red[tid * 4 + 3];
            if (APPLY_TANH) sv = tanhf(sv);
            outp[(size_t)(b0 + tid) * H + kk] = sv;
        }
    }
}

// ---------------------------------------------------------------------------
extern "C" void kernel_launch(void* const* d_in, const int* in_sizes, int n_in,
                              void* d_out, int out_size) {
    const float* h0  = (const float*)d_in[0];
    const float* ht  = (const float*)d_in[1];
    const float* msg = (const float*)d_in[2];
    const float* c   = (const float*)d_in[3];
    const float* fc1 = (const float*)d_in[4];
    const float* fc2 = (const float*)d_in[5];
    const float* fc3 = (const float*)d_in[6];
    const float* fc4 = (const float*)d_in[7];
    float* out = (float*)d_out;

    cudaFuncSetAttribute((const void*)hyper_mma_kernel<true>,
                         cudaFuncAttributeMaxDynamicSharedMemorySize, SMEM_TOTAL);
    cudaFuncSetAttribute((const void*)hyper_mma_kernel<false>,
                         cudaFuncAttributeMaxDynamicSharedMemorySize, SMEM_TOTAL);

    void* p_g1 = nullptr;
    cudaGetSymbolAddress(&p_g1, g_g1);

    // 1) MLP head -> x3 hi/lo
    mlp_head_kernel<<<B_TOTAL / 4, 128>>>(h0, ht, c, fc1, fc2, fc3);

    // 2) phase A: g1 = tanh( fold(msg, x3 @ W1^T) )
    hyper_mma_kernel<true><<<H, 256, SMEM_TOTAL>>>(fc4, msg, (float*)p_g1);

    // 3) phase B: out = fold(g1, x3 @ W2^T)
    hyper_mma_kernel<false><<<H, 256, SMEM_TOTAL>>>(
        fc4 + (size_t)H * H * HP, (const float*)p_g1, out);
}